// round 5
// baseline (speedup 1.0000x reference)
#include <cuda_runtime.h>
#include <cstdint>

#define BB   16
#define NN   16384
#define GS   16
#define GG   1024
#define HID  768
#define ED   384

// output layout (floats): tokens | centers | group_idx(as float)
#define TOK_OFF 0
#define CEN_OFF (BB*GG*ED)                 // 6291456
#define IDX_OFF (CEN_OFF + BB*GG*3)        // 6340608
#define TOT_SZ  (IDX_OFF + BB*GG*GS)       // 6602752

// device scratch (static allocation — no cudaMalloc allowed)
__device__ float g_mm[BB * 6];             // per batch: min x,y,z then max x,y,z
__device__ int   g_sidx[BB * NN];          // sorted indices per batch

__device__ __forceinline__ float gelu_exact(float x) {
    return 0.5f * x * (1.0f + erff(x * 0.70710678118654752f));
}

__device__ __forceinline__ int part1by2_10(int v) {
    v &= 1023;
    v = (v | (v << 16)) & 50331903;
    v = (v | (v << 8))  & 50393103;
    v = (v | (v << 4))  & 51130563;
    v = (v | (v << 2))  & 153391689;
    return v;
}

// ---------------- Kernel A: per-batch min/max ----------------
__global__ void k_minmax(const float* __restrict__ xyz) {
    int b = blockIdx.x;
    int t = threadIdx.x;
    const float* p = xyz + (size_t)b * NN * 3;
    float mn0 = 1e30f, mn1 = 1e30f, mn2 = 1e30f;
    float mx0 = -1e30f, mx1 = -1e30f, mx2 = -1e30f;
    for (int i = t; i < NN; i += blockDim.x) {
        float v0 = p[i * 3], v1 = p[i * 3 + 1], v2 = p[i * 3 + 2];
        mn0 = fminf(mn0, v0); mx0 = fmaxf(mx0, v0);
        mn1 = fminf(mn1, v1); mx1 = fmaxf(mx1, v1);
        mn2 = fminf(mn2, v2); mx2 = fmaxf(mx2, v2);
    }
    __shared__ float s[6][256];
    s[0][t] = mn0; s[1][t] = mn1; s[2][t] = mn2;
    s[3][t] = mx0; s[4][t] = mx1; s[5][t] = mx2;
    __syncthreads();
    for (int w = 128; w > 0; w >>= 1) {
        if (t < w) {
            #pragma unroll
            for (int c = 0; c < 3; c++) {
                s[c][t]     = fminf(s[c][t],     s[c][t + w]);
                s[c + 3][t] = fmaxf(s[c + 3][t], s[c + 3][t + w]);
            }
        }
        __syncthreads();
    }
    if (t < 6) g_mm[b * 6 + t] = s[t][0];
}

// ---------------- Kernel B: morton codes + bitonic argsort ----------------
// STABLE sort (packed unique keys: (code<<14)|idx -> ties ascending by index).
// Quantization: RECIPROCAL form  u = (x-mn) * rn(1/s), matching fast-math
// reciprocal substitution in the reference's compiled quantization.
__global__ void k_sort(const float* __restrict__ xyz, float* __restrict__ out, int out_size) {
    extern __shared__ unsigned long long keys[];
    int b = blockIdx.x;
    int t = threadIdx.x;
    float mn0 = g_mm[b * 6 + 0], mn1 = g_mm[b * 6 + 1], mn2 = g_mm[b * 6 + 2];
    float s0 = fmaxf(__fsub_rn(g_mm[b * 6 + 3], mn0), 1e-6f);
    float s1 = fmaxf(__fsub_rn(g_mm[b * 6 + 4], mn1), 1e-6f);
    float s2 = fmaxf(__fsub_rn(g_mm[b * 6 + 5], mn2), 1e-6f);
    float r0 = __fdiv_rn(1.0f, s0);
    float r1 = __fdiv_rn(1.0f, s1);
    float r2 = __fdiv_rn(1.0f, s2);
    const float* p = xyz + (size_t)b * NN * 3;

    for (int i = t; i < NN; i += blockDim.x) {
        float u0 = __fmul_rn(__fsub_rn(p[i * 3],     mn0), r0);
        float u1 = __fmul_rn(__fsub_rn(p[i * 3 + 1], mn1), r1);
        float u2 = __fmul_rn(__fsub_rn(p[i * 3 + 2], mn2), r2);
        int q0 = min(max(__float2int_rn(__fmul_rn(u0, 1023.0f)), 0), 1023);
        int q1 = min(max(__float2int_rn(__fmul_rn(u1, 1023.0f)), 0), 1023);
        int q2 = min(max(__float2int_rn(__fmul_rn(u2, 1023.0f)), 0), 1023);
        int code = part1by2_10(q0) | (part1by2_10(q1) << 1) | (part1by2_10(q2) << 2);
        keys[i] = ((unsigned long long)(unsigned)code << 14) | (unsigned long long)i;
    }
    __syncthreads();

    // bitonic sort, ascending, unique packed keys -> stable (ties asc by idx)
    for (int k = 2; k <= NN; k <<= 1) {
        for (int j = k >> 1; j > 0; j >>= 1) {
            for (int i = t; i < NN; i += blockDim.x) {
                int ixj = i ^ j;
                if (ixj > i) {
                    unsigned long long a = keys[i], c = keys[ixj];
                    bool up = ((i & k) == 0);
                    if ((a > c) == up) { keys[i] = c; keys[ixj] = a; }
                }
            }
            __syncthreads();
        }
    }

    for (int i = t; i < NN; i += blockDim.x) {
        int si = (int)(keys[i] & 16383ULL);
        g_sidx[b * NN + i] = si;
        if (out_size >= TOT_SZ) out[IDX_OFF + b * NN + i] = (float)si;
    }
}

// ---------------- Kernel C: gather + center + MLP + max + tokens ----------------
__global__ void __launch_bounds__(256) k_group(
    const float* __restrict__ xyz,
    const float* __restrict__ W1, const float* __restrict__ b1,
    const float* __restrict__ W2, const float* __restrict__ b2,
    const float* __restrict__ Wc, const float* __restrict__ bc,
    float* __restrict__ out, int out_size)
{
    extern __shared__ float sh[];
    float* Hsh   = sh;                        // 16*768 = 12288
    float* relsh = sh + GS * HID;             // 48
    float* smaxs = relsh + GS * 3;            // 4*384 = 1536
    float* csh   = smaxs + 4 * ED;            // 3

    int blk = blockIdx.x;
    int b = blk >> 10, g = blk & 1023;
    int t = threadIdx.x;

    // gather group points (already sorted order)
    if (t < GS) {
        int si = g_sidx[b * NN + g * GS + t];
        const float* pp = xyz + ((size_t)b * NN + si) * 3;
        relsh[t * 3 + 0] = pp[0];
        relsh[t * 3 + 1] = pp[1];
        relsh[t * 3 + 2] = pp[2];
    }
    __syncthreads();

    // center = mean over 16 points
    if (t < 3) {
        float sum = 0.f;
        #pragma unroll
        for (int p = 0; p < GS; p++) sum += relsh[p * 3 + t];
        float c = sum * (1.0f / GS);
        csh[t] = c;
        if (out_size >= CEN_OFF + BB * GG * 3)
            out[CEN_OFF + ((size_t)b * GG + g) * 3 + t] = c;
    }
    __syncthreads();

    if (t < GS * 3) relsh[t] -= csh[t % 3];
    __syncthreads();

    // layer 1: rel(16x3) @ W1(3x768) + b1 -> GELU -> Hsh
    for (int e = t; e < GS * HID; e += 256) {
        int p = e / HID;
        int k = e - p * HID;
        float v = relsh[p * 3] * W1[k]
                + relsh[p * 3 + 1] * W1[HID + k]
                + relsh[p * 3 + 2] * W1[2 * HID + k]
                + b1[k];
        Hsh[e] = gelu_exact(v);
    }
    __syncthreads();

    // layer 2: H(16x768) @ W2(768x384), register tile 4 pts x 6 cols per thread
    int ct = t & 63;          // 64 col-threads * 6 cols = 384
    int pt = t >> 6;          // 4 point-threads * 4 pts = 16
    int c0 = ct * 6;
    int p0 = pt * 4;

    float acc[4][6];
    #pragma unroll
    for (int j = 0; j < 4; j++)
        #pragma unroll
        for (int i = 0; i < 6; i++) acc[j][i] = 0.f;

    const float* Hp = Hsh + p0 * HID;
    #pragma unroll 4
    for (int k = 0; k < HID; k++) {
        float h0 = Hp[k];
        float h1 = Hp[HID + k];
        float h2 = Hp[2 * HID + k];
        float h3 = Hp[3 * HID + k];
        const float2* w = (const float2*)(W2 + (size_t)k * ED + c0);
        float2 wa = w[0], wb = w[1], wc2 = w[2];
        float ws[6] = {wa.x, wa.y, wb.x, wb.y, wc2.x, wc2.y};
        #pragma unroll
        for (int i = 0; i < 6; i++) {
            acc[0][i] = fmaf(h0, ws[i], acc[0][i]);
            acc[1][i] = fmaf(h1, ws[i], acc[1][i]);
            acc[2][i] = fmaf(h2, ws[i], acc[2][i]);
            acc[3][i] = fmaf(h3, ws[i], acc[3][i]);
        }
    }

    #pragma unroll
    for (int i = 0; i < 6; i++) {
        float bbias = b2[c0 + i];
        float m = gelu_exact(acc[0][i] + bbias);
        m = fmaxf(m, gelu_exact(acc[1][i] + bbias));
        m = fmaxf(m, gelu_exact(acc[2][i] + bbias));
        m = fmaxf(m, gelu_exact(acc[3][i] + bbias));
        smaxs[pt * ED + c0 + i] = m;
    }
    __syncthreads();

    // final max over the 4 point-groups + center projection
    for (int c = t; c < ED; c += 256) {
        float m = fmaxf(fmaxf(smaxs[c], smaxs[ED + c]),
                        fmaxf(smaxs[2 * ED + c], smaxs[3 * ED + c]));
        float tok = m
                  + csh[0] * Wc[c]
                  + csh[1] * Wc[ED + c]
                  + csh[2] * Wc[2 * ED + c]
                  + bc[c];
        out[TOK_OFF + ((size_t)b * GG + g) * ED + c] = tok;
    }
}

extern "C" void kernel_launch(void* const* d_in, const int* in_sizes, int n_in,
                              void* d_out, int out_size) {
    const float* xyz = (const float*)d_in[0];
    const float* W1  = (const float*)d_in[1];
    const float* b1  = (const float*)d_in[2];
    const float* W2  = (const float*)d_in[3];
    const float* b2  = (const float*)d_in[4];
    const float* Wc  = (const float*)d_in[5];
    const float* bc  = (const float*)d_in[6];
    float* out = (float*)d_out;

    const int sort_smem  = NN * 8;                                   // 131072
    const int group_smem = (GS * HID + GS * 3 + 4 * ED + 4) * 4;     // ~55.5 KB

    cudaFuncSetAttribute(k_sort,  cudaFuncAttributeMaxDynamicSharedMemorySize, sort_smem);
    cudaFuncSetAttribute(k_group, cudaFuncAttributeMaxDynamicSharedMemorySize, group_smem);

    k_minmax<<<BB, 256>>>(xyz);
    k_sort<<<BB, 1024, sort_smem>>>(xyz, out, out_size);
    k_group<<<BB * GG, 256, group_smem>>>(xyz, W1, b1, W2, b2, Wc, bc, out, out_size);
}

// round 6
// speedup vs baseline: 1.1165x; 1.1165x over previous
#include <cuda_runtime.h>
#include <cstdint>

#define BB   16
#define NN   16384
#define GS   16
#define GG   1024
#define HID  768
#define ED   384

// output layout (floats): tokens | centers | group_idx(as float)
#define TOK_OFF 0
#define CEN_OFF (BB*GG*ED)                 // 6291456
#define IDX_OFF (CEN_OFF + BB*GG*3)        // 6340608
#define TOT_SZ  (IDX_OFF + BB*GG*GS)       // 6602752

// k_group tiling
#define MT    32            // points per CTA (2 groups)
#define KC    32            // K-chunk
#define NCH   (HID/KC)      // 24 chunks

__device__ float g_mm[BB * 6];
__device__ int   g_sidx[BB * NN];

__device__ __forceinline__ float gelu_exact(float x) {
    return 0.5f * x * (1.0f + erff(x * 0.70710678118654752f));
}

__device__ __forceinline__ int part1by2_10(int v) {
    v &= 1023;
    v = (v | (v << 16)) & 50331903;
    v = (v | (v << 8))  & 50393103;
    v = (v | (v << 4))  & 51130563;
    v = (v | (v << 2))  & 153391689;
    return v;
}

// packed fp32x2 FMA (FFMA2) — only reachable via PTX
__device__ __forceinline__ void fma2(unsigned long long& d, unsigned long long a, unsigned long long b) {
    asm("fma.rn.f32x2 %0, %1, %2, %0;" : "+l"(d) : "l"(a), "l"(b));
}
__device__ __forceinline__ unsigned long long dup2(float w) {
    unsigned long long r;
    asm("mov.b64 %0, {%1, %1};" : "=l"(r) : "f"(w));
    return r;
}
__device__ __forceinline__ void unpack2(unsigned long long v, float& lo, float& hi) {
    asm("mov.b64 {%0, %1}, %2;" : "=f"(lo), "=f"(hi) : "l"(v));
}

// ---------------- Kernel A: per-batch min/max ----------------
__global__ void k_minmax(const float* __restrict__ xyz) {
    int b = blockIdx.x;
    int t = threadIdx.x;
    const float* p = xyz + (size_t)b * NN * 3;
    float mn0 = 1e30f, mn1 = 1e30f, mn2 = 1e30f;
    float mx0 = -1e30f, mx1 = -1e30f, mx2 = -1e30f;
    for (int i = t; i < NN; i += blockDim.x) {
        float v0 = p[i * 3], v1 = p[i * 3 + 1], v2 = p[i * 3 + 2];
        mn0 = fminf(mn0, v0); mx0 = fmaxf(mx0, v0);
        mn1 = fminf(mn1, v1); mx1 = fmaxf(mx1, v1);
        mn2 = fminf(mn2, v2); mx2 = fmaxf(mx2, v2);
    }
    __shared__ float s[6][256];
    s[0][t] = mn0; s[1][t] = mn1; s[2][t] = mn2;
    s[3][t] = mx0; s[4][t] = mx1; s[5][t] = mx2;
    __syncthreads();
    for (int w = 128; w > 0; w >>= 1) {
        if (t < w) {
            #pragma unroll
            for (int c = 0; c < 3; c++) {
                s[c][t]     = fminf(s[c][t],     s[c][t + w]);
                s[c + 3][t] = fmaxf(s[c + 3][t], s[c + 3][t + w]);
            }
        }
        __syncthreads();
    }
    if (t < 6) g_mm[b * 6 + t] = s[t][0];
}

// ---------------- Kernel B: morton + stable bitonic argsort (FROZEN) ----------------
__global__ void k_sort(const float* __restrict__ xyz, float* __restrict__ out, int out_size) {
    extern __shared__ unsigned long long keys[];
    int b = blockIdx.x;
    int t = threadIdx.x;
    float mn0 = g_mm[b * 6 + 0], mn1 = g_mm[b * 6 + 1], mn2 = g_mm[b * 6 + 2];
    float s0 = fmaxf(__fsub_rn(g_mm[b * 6 + 3], mn0), 1e-6f);
    float s1 = fmaxf(__fsub_rn(g_mm[b * 6 + 4], mn1), 1e-6f);
    float s2 = fmaxf(__fsub_rn(g_mm[b * 6 + 5], mn2), 1e-6f);
    float r0 = __fdiv_rn(1.0f, s0);
    float r1 = __fdiv_rn(1.0f, s1);
    float r2 = __fdiv_rn(1.0f, s2);
    const float* p = xyz + (size_t)b * NN * 3;

    for (int i = t; i < NN; i += blockDim.x) {
        float u0 = __fmul_rn(__fsub_rn(p[i * 3],     mn0), r0);
        float u1 = __fmul_rn(__fsub_rn(p[i * 3 + 1], mn1), r1);
        float u2 = __fmul_rn(__fsub_rn(p[i * 3 + 2], mn2), r2);
        int q0 = min(max(__float2int_rn(__fmul_rn(u0, 1023.0f)), 0), 1023);
        int q1 = min(max(__float2int_rn(__fmul_rn(u1, 1023.0f)), 0), 1023);
        int q2 = min(max(__float2int_rn(__fmul_rn(u2, 1023.0f)), 0), 1023);
        int code = part1by2_10(q0) | (part1by2_10(q1) << 1) | (part1by2_10(q2) << 2);
        keys[i] = ((unsigned long long)(unsigned)code << 14) | (unsigned long long)i;
    }
    __syncthreads();

    for (int k = 2; k <= NN; k <<= 1) {
        for (int j = k >> 1; j > 0; j >>= 1) {
            for (int i = t; i < NN; i += blockDim.x) {
                int ixj = i ^ j;
                if (ixj > i) {
                    unsigned long long a = keys[i], c = keys[ixj];
                    bool up = ((i & k) == 0);
                    if ((a > c) == up) { keys[i] = c; keys[ixj] = a; }
                }
            }
            __syncthreads();
        }
    }

    for (int i = t; i < NN; i += blockDim.x) {
        int si = (int)(keys[i] & 16383ULL);
        g_sidx[b * NN + i] = si;
        if (out_size >= TOT_SZ) out[IDX_OFF + b * NN + i] = (float)si;
    }
}

// ---------------- Kernel C: 32-pt tile, smem W2, FFMA2 layer-2 ----------------
// thread map: c = t & 63 (col-thread), pp = t >> 6 (point-pair thread, 0..3)
// cols per thread: c + 64*i  (i=0..5), scalar, conflict-free LDS.32
// points per thread: pairs q = pp*4 + j (j=0..3) -> points {2q, 2q+1}
//   pp 0,1 -> group 0 ; pp 2,3 -> group 1
__global__ void __launch_bounds__(256, 2) k_group(
    const float* __restrict__ xyz,
    const float* __restrict__ W1, const float* __restrict__ b1,
    const float* __restrict__ W2, const float* __restrict__ b2,
    const float* __restrict__ Wc, const float* __restrict__ bc,
    float* __restrict__ out, int out_size)
{
    extern __shared__ float sh[];
    float* W2s  = sh;                        // KC*384 = 12288 floats (49152 B)
    float* Hs   = W2s + KC * ED;             // KC*MT  = 1024 floats  [k][p]
    float* rel  = Hs + KC * MT;              // MT*3   = 96
    float* cen  = rel + MT * 3;              // 2*3    = 6 (+2 pad)
    float* smax = cen + 8;                   // 4*384  = 1536

    int blk = blockIdx.x;                    // 8192 blocks
    int b  = blk >> 9;
    int gb = blk & 511;                      // 2 groups per CTA
    int m0 = gb * MT;                        // base point (sorted order)
    int t  = threadIdx.x;
    int c  = t & 63;
    int pp = t >> 6;

    // gather 32 sorted points
    if (t < MT) {
        int si = g_sidx[b * NN + m0 + t];
        const float* ppt = xyz + ((size_t)b * NN + si) * 3;
        rel[t * 3 + 0] = ppt[0];
        rel[t * 3 + 1] = ppt[1];
        rel[t * 3 + 2] = ppt[2];
    }
    __syncthreads();

    // per-group centers (2 groups x 3 coords)
    if (t < 6) {
        int g = t / 3, cc = t % 3;
        float sum = 0.f;
        #pragma unroll
        for (int p = 0; p < GS; p++) sum += rel[(g * GS + p) * 3 + cc];
        float cv = sum * (1.0f / GS);
        cen[t] = cv;
        if (out_size >= CEN_OFF + BB * GG * 3)
            out[CEN_OFF + ((size_t)b * GG + gb * 2 + g) * 3 + cc] = cv;
    }
    __syncthreads();
    if (t < MT * 3) rel[t] -= cen[(t / (GS * 3)) * 3 + t % 3];
    __syncthreads();

    // accumulators: 4 point-pairs x 6 cols, packed fp32x2 over the point pair
    unsigned long long acc[4][6];
    #pragma unroll
    for (int j = 0; j < 4; j++)
        #pragma unroll
        for (int i = 0; i < 6; i++) acc[j][i] = 0ULL;

    for (int kc = 0; kc < NCH; kc++) {
        __syncthreads();   // protect previous chunk's Hs/W2s reads
        // stage W2 chunk [KC x 384] via float4
        {
            const float4* src = (const float4*)(W2 + (size_t)kc * KC * ED);
            float4* dst = (float4*)W2s;
            #pragma unroll
            for (int idx = t; idx < KC * ED / 4; idx += 256) dst[idx] = src[idx];
        }
        // layer 1 for this chunk: Hs[k][p] = gelu(rel[p] . W1[:,kk] + b1[kk])
        {
            #pragma unroll
            for (int e = t; e < KC * MT; e += 256) {
                int k = e >> 5, p = e & 31;
                int kk = kc * KC + k;
                float v = rel[p * 3 + 0] * W1[kk]
                        + rel[p * 3 + 1] * W1[HID + kk]
                        + rel[p * 3 + 2] * W1[2 * HID + kk]
                        + b1[kk];
                Hs[k * MT + p] = gelu_exact(v);
            }
        }
        __syncthreads();

        // layer-2 inner loop: 24 FFMA2 per k per thread
        #pragma unroll 8
        for (int k = 0; k < KC; k++) {
            const unsigned long long* hrow = (const unsigned long long*)(Hs + k * MT);
            unsigned long long hp0 = hrow[pp * 4 + 0];
            unsigned long long hp1 = hrow[pp * 4 + 1];
            unsigned long long hp2 = hrow[pp * 4 + 2];
            unsigned long long hp3 = hrow[pp * 4 + 3];
            const float* wrow = W2s + k * ED + c;
            #pragma unroll
            for (int i = 0; i < 6; i++) {
                unsigned long long w2 = dup2(wrow[i * 64]);
                fma2(acc[0][i], hp0, w2);
                fma2(acc[1][i], hp1, w2);
                fma2(acc[2][i], hp2, w2);
                fma2(acc[3][i], hp3, w2);
            }
        }
    }

    // epilogue: bias + gelu + max over this thread's 8 points, per col
    #pragma unroll
    for (int i = 0; i < 6; i++) {
        int colg = c + 64 * i;
        float bbias = b2[colg];
        float m = -1e30f;
        #pragma unroll
        for (int j = 0; j < 4; j++) {
            float a0, a1;
            unpack2(acc[j][i], a0, a1);
            m = fmaxf(m, gelu_exact(a0 + bbias));
            m = fmaxf(m, gelu_exact(a1 + bbias));
        }
        smax[pp * ED + colg] = m;
    }
    __syncthreads();

    // final per-group max (pp0+pp1 -> g0, pp2+pp3 -> g1) + center projection
    for (int idx = t; idx < 2 * ED; idx += 256) {
        int g = idx / ED, colg = idx % ED;
        float m = fmaxf(smax[(2 * g) * ED + colg], smax[(2 * g + 1) * ED + colg]);
        float tok = m
                  + cen[g * 3 + 0] * Wc[colg]
                  + cen[g * 3 + 1] * Wc[ED + colg]
                  + cen[g * 3 + 2] * Wc[2 * ED + colg]
                  + bc[colg];
        out[TOK_OFF + ((size_t)b * GG + gb * 2 + g) * ED + colg] = tok;
    }
}

extern "C" void kernel_launch(void* const* d_in, const int* in_sizes, int n_in,
                              void* d_out, int out_size) {
    const float* xyz = (const float*)d_in[0];
    const float* W1  = (const float*)d_in[1];
    const float* b1  = (const float*)d_in[2];
    const float* W2  = (const float*)d_in[3];
    const float* b2  = (const float*)d_in[4];
    const float* Wc  = (const float*)d_in[5];
    const float* bc  = (const float*)d_in[6];
    float* out = (float*)d_out;

    const int sort_smem  = NN * 8;                                     // 131072
    const int group_smem = (KC * ED + KC * MT + MT * 3 + 8 + 4 * ED) * 4; // ~59.6 KB

    cudaFuncSetAttribute(k_sort,  cudaFuncAttributeMaxDynamicSharedMemorySize, sort_smem);
    cudaFuncSetAttribute(k_group, cudaFuncAttributeMaxDynamicSharedMemorySize, group_smem);

    k_minmax<<<BB, 256>>>(xyz);
    k_sort<<<BB, 1024, sort_smem>>>(xyz, out, out_size);
    k_group<<<BB * GG / 2, 256, group_smem>>>(xyz, W1, b1, W2, b2, Wc, bc, out, out_size);
}

// round 8
// speedup vs baseline: 1.5853x; 1.4199x over previous
#include <cuda_runtime.h>
#include <cuda_bf16.h>
#include <cstdint>

#define BB   16
#define NN   16384
#define GS   16
#define GG   1024
#define HID  768
#define ED   384

// output layout (floats): tokens | centers | group_idx(as float)
#define TOK_OFF 0
#define CEN_OFF (BB*GG*ED)
#define IDX_OFF (CEN_OFF + BB*GG*3)
#define TOT_SZ  (IDX_OFF + BB*GG*GS)

// GEMM tiling
#define NPT 128                  // points per CTA (8 groups)
#define KCH 64                   // K chunk
#define NKC (HID/KCH)            // 12
#define TILE_B 16384             // one 128x64 bf16 tile

// smem layout (bytes)
#define SM_W2(bi) ((bi)*32768)            // hi +0, lo +16384
#define SM_H(bi)  (65536 + (bi)*32768)    // hi +0, lo +16384
#define SM_REL    131072                  // 384 floats
#define SM_CEN    132608                  // 24 floats
#define SM_TOTAL  132736

__device__ float g_mm[BB * 6];
__device__ int   g_sidx[BB * NN];
__device__ __align__(16) char g_w2hi[3 * NKC * TILE_B];
__device__ __align__(16) char g_w2lo[3 * NKC * TILE_B];

__device__ __forceinline__ float gelu_exact(float x) {
    return 0.5f * x * (1.0f + erff(x * 0.70710678118654752f));
}
__device__ __forceinline__ int part1by2_10(int v) {
    v &= 1023;
    v = (v | (v << 16)) & 50331903;
    v = (v | (v << 8))  & 50393103;
    v = (v | (v << 4))  & 51130563;
    v = (v | (v << 2))  & 153391689;
    return v;
}
__device__ __forceinline__ uint32_t smem_u32(const void* p) {
    uint32_t a;
    asm("{ .reg .u64 t; cvta.to.shared.u64 t, %1; cvt.u32.u64 %0, t; }" : "=r"(a) : "l"(p));
    return a;
}
__device__ __forceinline__ void ldmx4(uint32_t* r, uint32_t a) {
    asm volatile("ldmatrix.sync.aligned.m8n8.x4.shared.b16 {%0,%1,%2,%3}, [%4];"
        : "=r"(r[0]), "=r"(r[1]), "=r"(r[2]), "=r"(r[3]) : "r"(a));
}
__device__ __forceinline__ void ldmx2(uint32_t* r, uint32_t a) {
    asm volatile("ldmatrix.sync.aligned.m8n8.x2.shared.b16 {%0,%1}, [%2];"
        : "=r"(r[0]), "=r"(r[1]) : "r"(a));
}
__device__ __forceinline__ void mma16816(float* c, const uint32_t* a, const uint32_t* b) {
    asm volatile(
        "mma.sync.aligned.m16n8k16.row.col.f32.bf16.bf16.f32 "
        "{%0,%1,%2,%3}, {%4,%5,%6,%7}, {%8,%9}, {%0,%1,%2,%3};"
        : "+f"(c[0]), "+f"(c[1]), "+f"(c[2]), "+f"(c[3])
        : "r"(a[0]), "r"(a[1]), "r"(a[2]), "r"(a[3]), "r"(b[0]), "r"(b[1]));
}

// ---------------- Kernel A: per-batch min/max (FROZEN) ----------------
__global__ void k_minmax(const float* __restrict__ xyz) {
    int b = blockIdx.x;
    int t = threadIdx.x;
    const float* p = xyz + (size_t)b * NN * 3;
    float mn0 = 1e30f, mn1 = 1e30f, mn2 = 1e30f;
    float mx0 = -1e30f, mx1 = -1e30f, mx2 = -1e30f;
    for (int i = t; i < NN; i += blockDim.x) {
        float v0 = p[i * 3], v1 = p[i * 3 + 1], v2 = p[i * 3 + 2];
        mn0 = fminf(mn0, v0); mx0 = fmaxf(mx0, v0);
        mn1 = fminf(mn1, v1); mx1 = fmaxf(mx1, v1);
        mn2 = fminf(mn2, v2); mx2 = fmaxf(mx2, v2);
    }
    __shared__ float s[6][256];
    s[0][t] = mn0; s[1][t] = mn1; s[2][t] = mn2;
    s[3][t] = mx0; s[4][t] = mx1; s[5][t] = mx2;
    __syncthreads();
    for (int w = 128; w > 0; w >>= 1) {
        if (t < w) {
            #pragma unroll
            for (int c = 0; c < 3; c++) {
                s[c][t]     = fminf(s[c][t],     s[c][t + w]);
                s[c + 3][t] = fmaxf(s[c + 3][t], s[c + 3][t + w]);
            }
        }
        __syncthreads();
    }
    if (t < 6) g_mm[b * 6 + t] = s[t][0];
}

// ---------------- Kernel B: morton + stable bitonic argsort (FROZEN) ----------------
__global__ void k_sort(const float* __restrict__ xyz, float* __restrict__ out, int out_size) {
    extern __shared__ unsigned long long keys[];
    int b = blockIdx.x;
    int t = threadIdx.x;
    float mn0 = g_mm[b * 6 + 0], mn1 = g_mm[b * 6 + 1], mn2 = g_mm[b * 6 + 2];
    float s0 = fmaxf(__fsub_rn(g_mm[b * 6 + 3], mn0), 1e-6f);
    float s1 = fmaxf(__fsub_rn(g_mm[b * 6 + 4], mn1), 1e-6f);
    float s2 = fmaxf(__fsub_rn(g_mm[b * 6 + 5], mn2), 1e-6f);
    float r0 = __fdiv_rn(1.0f, s0);
    float r1 = __fdiv_rn(1.0f, s1);
    float r2 = __fdiv_rn(1.0f, s2);
    const float* p = xyz + (size_t)b * NN * 3;

    for (int i = t; i < NN; i += blockDim.x) {
        float u0 = __fmul_rn(__fsub_rn(p[i * 3],     mn0), r0);
        float u1 = __fmul_rn(__fsub_rn(p[i * 3 + 1], mn1), r1);
        float u2 = __fmul_rn(__fsub_rn(p[i * 3 + 2], mn2), r2);
        int q0 = min(max(__float2int_rn(__fmul_rn(u0, 1023.0f)), 0), 1023);
        int q1 = min(max(__float2int_rn(__fmul_rn(u1, 1023.0f)), 0), 1023);
        int q2 = min(max(__float2int_rn(__fmul_rn(u2, 1023.0f)), 0), 1023);
        int code = part1by2_10(q0) | (part1by2_10(q1) << 1) | (part1by2_10(q2) << 2);
        keys[i] = ((unsigned long long)(unsigned)code << 14) | (unsigned long long)i;
    }
    __syncthreads();

    for (int k = 2; k <= NN; k <<= 1) {
        for (int j = k >> 1; j > 0; j >>= 1) {
            for (int i = t; i < NN; i += blockDim.x) {
                int ixj = i ^ j;
                if (ixj > i) {
                    unsigned long long a = keys[i], c = keys[ixj];
                    bool up = ((i & k) == 0);
                    if ((a > c) == up) { keys[i] = c; keys[ixj] = a; }
                }
            }
            __syncthreads();
        }
    }

    for (int i = t; i < NN; i += blockDim.x) {
        int si = (int)(keys[i] & 16383ULL);
        g_sidx[b * NN + i] = si;
        if (out_size >= TOT_SZ) out[IDX_OFF + b * NN + i] = (float)si;
    }
}

// ---------------- Kernel P: W2 -> bf16 hi/lo transposed + swizzled tiles ----------------
__global__ void k_prep(const float* __restrict__ W2) {
    int idx = blockIdx.x * 256 + threadIdx.x;
    if (idx >= HID * ED) return;
    int k = idx / ED, n = idx - k * ED;
    float w = W2[idx];
    __nv_bfloat16 hi = __float2bfloat16(w);
    __nv_bfloat16 lo = __float2bfloat16(w - __bfloat162float(hi));
    int mc = n >> 7, row = n & 127, kc = k >> 6, col = k & 63;
    uint32_t off = (uint32_t)(row * 128 + col * 2);
    off ^= (off >> 3) & 0x70;
    size_t tile = (size_t)(mc * NKC + kc) * TILE_B;
    *(__nv_bfloat16*)(g_w2hi + tile + off) = hi;
    *(__nv_bfloat16*)(g_w2lo + tile + off) = lo;
}

// ---------------- Kernel C: fused gather + MLP via mma.sync split-bf16 ----------------
__global__ void __launch_bounds__(256, 1) k_gemm(
    const float* __restrict__ xyz,
    const float* __restrict__ W1, const float* __restrict__ b1,
    const float* __restrict__ b2,
    const float* __restrict__ Wc, const float* __restrict__ bc,
    float* __restrict__ out, int out_size)
{
    extern __shared__ char sm[];
    uint32_t smb = smem_u32(sm);
    float* rel = (float*)(sm + SM_REL);
    float* cen = (float*)(sm + SM_CEN);

    int t = threadIdx.x, wid = t >> 5, lane = t & 31;
    int blk = blockIdx.x;                 // 2048
    int b = blk >> 7;
    int chunk = blk & 127;
    int gbase = chunk * 8;
    int m0 = chunk * NPT;

    // gather sorted points
    if (t < NPT) {
        int si = g_sidx[b * NN + m0 + t];
        const float* pp = xyz + ((size_t)b * NN + si) * 3;
        rel[t * 3 + 0] = pp[0];
        rel[t * 3 + 1] = pp[1];
        rel[t * 3 + 2] = pp[2];
    }
    __syncthreads();
    if (t < 24) {
        int g = t / 3, cc = t - g * 3;
        float sum = 0.f;
        #pragma unroll
        for (int p = 0; p < GS; p++) sum += rel[(g * GS + p) * 3 + cc];
        float cv = sum * (1.0f / GS);
        cen[t] = cv;
        if (out_size >= CEN_OFF + BB * GG * 3)
            out[CEN_OFF + ((size_t)b * GG + gbase + g) * 3 + cc] = cv;
    }
    __syncthreads();
    for (int i = t; i < NPT * 3; i += 256) rel[i] -= cen[(i / (GS * 3)) * 3 + i % 3];
    __syncthreads();

    int p = t & 127;
    float rx = rel[p * 3], ry = rel[p * 3 + 1], rz = rel[p * 3 + 2];
    int kb = t >> 7;

    // layer-1 + gelu + split for K-chunk kc into H buffer hb
    auto computeH = [&](int kc, int hb) {
        char* hbp = sm + SM_H(hb);
        #pragma unroll 4
        for (int i = 0; i < 32; i++) {
            int k = kb + i * 2;
            int kk = kc * KCH + k;
            float v = fmaf(rx, W1[kk], fmaf(ry, W1[HID + kk], fmaf(rz, W1[2 * HID + kk], b1[kk])));
            float h = gelu_exact(v);
            __nv_bfloat16 hi = __float2bfloat16(h);
            __nv_bfloat16 lo = __float2bfloat16(h - __bfloat162float(hi));
            uint32_t off = (uint32_t)(p * 128 + k * 2);
            off ^= (off >> 3) & 0x70;
            *(__nv_bfloat16*)(hbp + off) = hi;
            *(__nv_bfloat16*)(hbp + 16384 + off) = lo;
        }
    };

    // cp.async stage of one pre-swizzled W2 tile pair into buffer bi
    auto cp_issue = [&](int mc, int kc, int bi) {
        size_t tile = (size_t)(mc * NKC + kc) * TILE_B;
        const char* sh = g_w2hi + tile;
        const char* sl = g_w2lo + tile;
        uint32_t dh = smb + SM_W2(bi);
        #pragma unroll
        for (int i = 0; i < 4; i++) {
            uint32_t o = (uint32_t)(t * 16 + i * 4096);
            asm volatile("cp.async.cg.shared.global [%0], [%1], 16;"
                :: "r"(dh + o), "l"(__cvta_generic_to_global(sh + o)) : "memory");
            asm volatile("cp.async.cg.shared.global [%0], [%1], 16;"
                :: "r"(dh + 16384 + o), "l"(__cvta_generic_to_global(sl + o)) : "memory");
        }
        asm volatile("cp.async.commit_group;" ::: "memory");
    };

    int m0w = (wid & 3) * 32;      // warp M offset (embed cols within 128)
    int n0w = (wid >> 2) * 64;     // warp N offset (points)

    for (int mc = 0; mc < 3; mc++) {
        float c[2][8][4];
        #pragma unroll
        for (int mf = 0; mf < 2; mf++)
            #pragma unroll
            for (int nf = 0; nf < 8; nf++)
                #pragma unroll
                for (int q = 0; q < 4; q++) c[mf][nf][q] = 0.f;

        cp_issue(mc, 0, 0);
        cp_issue(mc, 1, 1);
        computeH(0, 0);

        for (int kc = 0; kc < NKC; kc++) {
            int bi = kc & 1;
            if (kc < NKC - 1) { asm volatile("cp.async.wait_group 1;" ::: "memory"); }
            else              { asm volatile("cp.async.wait_group 0;" ::: "memory"); }
            __syncthreads();

            uint32_t wbase = smb + SM_W2(bi);
            uint32_t hbase = smb + SM_H(bi);
            #pragma unroll
            for (int ks = 0; ks < 4; ks++) {
                uint32_t ahi[2][4], alo[2][4];
                #pragma unroll
                for (int mf = 0; mf < 2; mf++) {
                    uint32_t offA = (uint32_t)((m0w + mf * 16 + (lane & 15)) * 128
                                   + ks * 32 + ((lane >> 4) << 4));
                    offA ^= (offA >> 3) & 0x70;
                    ldmx4(ahi[mf], wbase + offA);
                    ldmx4(alo[mf], wbase + 16384 + offA);
                }
                #pragma unroll
                for (int nf = 0; nf < 8; nf++) {
                    uint32_t bhi[2], blo[2];
                    uint32_t offB = (uint32_t)((n0w + nf * 8 + (lane & 7)) * 128
                                   + ks * 32 + (((lane >> 3) & 1) << 4));
                    offB ^= (offB >> 3) & 0x70;
                    ldmx2(bhi, hbase + offB);
                    ldmx2(blo, hbase + 16384 + offB);
                    #pragma unroll
                    for (int mf = 0; mf < 2; mf++) {
                        mma16816(c[mf][nf], ahi[mf], bhi);
                        mma16816(c[mf][nf], ahi[mf], blo);
                        mma16816(c[mf][nf], alo[mf], bhi);
                    }
                }
            }
            __syncthreads();

            if (kc + 2 < NKC) cp_issue(mc, kc + 2, bi);
            if (kc + 1 < NKC) computeH(kc + 1, (kc + 1) & 1);
        }

        // epilogue: bias + gelu + group max (quad shuffle) + center proj
        #pragma unroll
        for (int mf = 0; mf < 2; mf++) {
            int row0 = mc * 128 + m0w + mf * 16 + (lane >> 2);
            int row1 = row0 + 8;
            float bias0 = b2[row0], bias1 = b2[row1];
            #pragma unroll
            for (int g = 0; g < 4; g++) {
                float va = -1e30f, vb = -1e30f;
                #pragma unroll
                for (int q = 0; q < 2; q++) {
                    float* cc = c[mf][2 * g + q];
                    va = fmaxf(va, fmaxf(gelu_exact(cc[0] + bias0), gelu_exact(cc[1] + bias0)));
                    vb = fmaxf(vb, fmaxf(gelu_exact(cc[2] + bias1), gelu_exact(cc[3] + bias1)));
                }
                va = fmaxf(va, __shfl_xor_sync(0xffffffffu, va, 1));
                va = fmaxf(va, __shfl_xor_sync(0xffffffffu, va, 2));
                vb = fmaxf(vb, __shfl_xor_sync(0xffffffffu, vb, 1));
                vb = fmaxf(vb, __shfl_xor_sync(0xffffffffu, vb, 2));
                if ((lane & 3) == 0) {
                    int gl = (wid >> 2) * 4 + g;
                    int gg = gbase + gl;
                    float c0_ = cen[gl * 3], c1_ = cen[gl * 3 + 1], c2_ = cen[gl * 3 + 2];
                    out[TOK_OFF + ((size_t)b * GG + gg) * ED + row0] =
                        va + c0_ * Wc[row0] + c1_ * Wc[ED + row0] + c2_ * Wc[2 * ED + row0] + bc[row0];
                    out[TOK_OFF + ((size_t)b * GG + gg) * ED + row1] =
                        vb + c0_ * Wc[row1] + c1_ * Wc[ED + row1] + c2_ * Wc[2 * ED + row1] + bc[row1];
                }
            }
        }
        __syncthreads();
    }
}

extern "C" void kernel_launch(void* const* d_in, const int* in_sizes, int n_in,
                              void* d_out, int out_size) {
    const float* xyz = (const float*)d_in[0];
    const float* W1  = (const float*)d_in[1];
    const float* b1  = (const float*)d_in[2];
    const float* W2  = (const float*)d_in[3];
    const float* b2  = (const float*)d_in[4];
    const float* Wc  = (const float*)d_in[5];
    const float* bc  = (const float*)d_in[6];
    float* out = (float*)d_out;

    const int sort_smem = NN * 8;
    cudaFuncSetAttribute(k_sort, cudaFuncAttributeMaxDynamicSharedMemorySize, sort_smem);
    cudaFuncSetAttribute(k_gemm, cudaFuncAttributeMaxDynamicSharedMemorySize, SM_TOTAL);

    k_minmax<<<BB, 256>>>(xyz);
    k_sort<<<BB, 1024, sort_smem>>>(xyz, out, out_size);
    k_prep<<<(HID * ED + 255) / 256, 256>>>(W2);
    k_gemm<<<BB * NN / NPT, 256, SM_TOTAL>>>(xyz, W1, b1, b2, Wc, bc, out, out_size);
}